// round 2
// baseline (speedup 1.0000x reference)
#include <cuda_runtime.h>
#include <cstdint>

// Problem dims (fixed)
#define B_  16
#define U_  64
#define T_  128
#define E_  128
#define HID_ 256
#define H_  4
#define ENC_H_ 128
#define IN_DIM_ 32

// Scratch (device globals: no allocation allowed)
__device__ float g_qu[B_ * U_ * HID_];   // ue @ fw1[:E]          (1024 x 256)
__device__ float g_kh[B_ * T_ * HID_];   // te @ fw1[E:]          (2048 x 256)
__device__ float g_qb[H_ * HID_];        // head_q @ fw1[:E] + fb1 (4 x 256)

// ---------------------------------------------------------------------------
// Fused encoder: x(rows,32) -> relu(.@w0+b0) -> relu(.@w1+b1) -> (.@w2+b2)
//                -> (. @ fw1[fw1_off : fw1_off+128, :])  stored to g_qu/g_kh
// One block = 16 rows, 128 threads (thread j owns output column j).
// ---------------------------------------------------------------------------
__global__ __launch_bounds__(128) void enc_kernel(
    const float* __restrict__ x,
    const float* __restrict__ w0, const float* __restrict__ b0,
    const float* __restrict__ w1, const float* __restrict__ b1,
    const float* __restrict__ w2, const float* __restrict__ b2,
    const float* __restrict__ fw1, int fw1_off, int sel)
{
    __shared__ float xs[16][IN_DIM_];
    __shared__ float bufA[16][ENC_H_];
    __shared__ float bufB[16][ENC_H_];

    const int tid = threadIdx.x;
    const int row0 = blockIdx.x * 16;
    float* out = sel ? g_kh : g_qu;

    // load 16x32 input tile
    for (int i = tid; i < 16 * IN_DIM_; i += 128) {
        xs[i >> 5][i & 31] = x[(row0 + (i >> 5)) * IN_DIM_ + (i & 31)];
    }
    __syncthreads();

    const int j = tid;
    float acc[16];

    // ---- layer 0: 32 -> 128, relu ----
    #pragma unroll
    for (int r = 0; r < 16; ++r) acc[r] = b0[j];
    #pragma unroll
    for (int k = 0; k < IN_DIM_; k += 4) {
        float wv0 = w0[(k + 0) * ENC_H_ + j];
        float wv1 = w0[(k + 1) * ENC_H_ + j];
        float wv2 = w0[(k + 2) * ENC_H_ + j];
        float wv3 = w0[(k + 3) * ENC_H_ + j];
        #pragma unroll
        for (int r = 0; r < 16; ++r) {
            float4 xa = *(const float4*)&xs[r][k];
            acc[r] += xa.x * wv0 + xa.y * wv1 + xa.z * wv2 + xa.w * wv3;
        }
    }
    #pragma unroll
    for (int r = 0; r < 16; ++r) bufA[r][j] = fmaxf(acc[r], 0.f);
    __syncthreads();

    // ---- layer 1: 128 -> 128, relu ----
    #pragma unroll
    for (int r = 0; r < 16; ++r) acc[r] = b1[j];
    #pragma unroll 8
    for (int k = 0; k < ENC_H_; k += 4) {
        float wv0 = w1[(k + 0) * ENC_H_ + j];
        float wv1 = w1[(k + 1) * ENC_H_ + j];
        float wv2 = w1[(k + 2) * ENC_H_ + j];
        float wv3 = w1[(k + 3) * ENC_H_ + j];
        #pragma unroll
        for (int r = 0; r < 16; ++r) {
            float4 xa = *(const float4*)&bufA[r][k];
            acc[r] += xa.x * wv0 + xa.y * wv1 + xa.z * wv2 + xa.w * wv3;
        }
    }
    #pragma unroll
    for (int r = 0; r < 16; ++r) bufB[r][j] = fmaxf(acc[r], 0.f);
    __syncthreads();

    // ---- layer 2: 128 -> 128 (no relu) ----
    #pragma unroll
    for (int r = 0; r < 16; ++r) acc[r] = b2[j];
    #pragma unroll 8
    for (int k = 0; k < ENC_H_; k += 4) {
        float wv0 = w2[(k + 0) * ENC_H_ + j];
        float wv1 = w2[(k + 1) * ENC_H_ + j];
        float wv2 = w2[(k + 2) * ENC_H_ + j];
        float wv3 = w2[(k + 3) * ENC_H_ + j];
        #pragma unroll
        for (int r = 0; r < 16; ++r) {
            float4 xa = *(const float4*)&bufB[r][k];
            acc[r] += xa.x * wv0 + xa.y * wv1 + xa.z * wv2 + xa.w * wv3;
        }
    }
    __syncthreads();   // bufA free to overwrite
    #pragma unroll
    for (int r = 0; r < 16; ++r) bufA[r][j] = acc[r];
    __syncthreads();

    // ---- projection through fw1 slice: 128 -> 256 ----
    for (int jj = j; jj < HID_; jj += 128) {
        #pragma unroll
        for (int r = 0; r < 16; ++r) acc[r] = 0.f;
        #pragma unroll 8
        for (int k = 0; k < E_; k += 4) {
            float wv0 = fw1[(fw1_off + k + 0) * HID_ + jj];
            float wv1 = fw1[(fw1_off + k + 1) * HID_ + jj];
            float wv2 = fw1[(fw1_off + k + 2) * HID_ + jj];
            float wv3 = fw1[(fw1_off + k + 3) * HID_ + jj];
            #pragma unroll
            for (int r = 0; r < 16; ++r) {
                float4 xa = *(const float4*)&bufA[r][k];
                acc[r] += xa.x * wv0 + xa.y * wv1 + xa.z * wv2 + xa.w * wv3;
            }
        }
        #pragma unroll
        for (int r = 0; r < 16; ++r) out[(size_t)(row0 + r) * HID_ + jj] = acc[r];
    }
}

// ---------------------------------------------------------------------------
// qb[h][d] = fb1[d] + sum_k head_q[h][k] * fw1[k][d]
// ---------------------------------------------------------------------------
__global__ __launch_bounds__(256) void qb_kernel(
    const float* __restrict__ head_q, const float* __restrict__ fw1,
    const float* __restrict__ fb1)
{
    int h = blockIdx.x;
    int d = threadIdx.x;
    float acc = fb1[d];
    #pragma unroll 8
    for (int k = 0; k < E_; ++k)
        acc += head_q[h * E_ + k] * fw1[k * HID_ + d];
    g_qb[h * HID_ + d] = acc;
}

// ---------------------------------------------------------------------------
// Stage E: logits[b,h,u,t] = fb2 + sum_d relu(qu[b,u,d]+qb[h,d]+kh[b,t,d])*fw2[d]
// Block tile: 16 u x 64 t, 256 threads; thread = (u, 4 consecutive t).
// kh tile stored transposed in smem [d][t] (row stride 68 for alignment).
// ---------------------------------------------------------------------------
#define KS_STRIDE 68
#define SMEM_E_FLOATS (16 * HID_ + HID_ * KS_STRIDE + HID_)
#define SMEM_E_BYTES  (SMEM_E_FLOATS * 4)

__global__ __launch_bounds__(256) void stageE_kernel(
    const float* __restrict__ fw2, const float* __restrict__ fb2,
    float* __restrict__ out)
{
    extern __shared__ float smem[];
    float* qs   = smem;                       // [16][256]
    float* ks   = smem + 16 * HID_;           // [256][68]
    float* fw2s = ks + HID_ * KS_STRIDE;      // [256]

    const int tid = threadIdx.x;
    const int t0 = blockIdx.x * 64;
    const int u0 = blockIdx.y * 16;
    const int z  = blockIdx.z;                // b*H + h
    const int b  = z >> 2;
    const int h  = z & 3;

    // --- fill qs = qu + qb (float4) ---
    {
        const float4* qb4 = (const float4*)(g_qb + h * HID_);
        for (int idx = tid; idx < 16 * (HID_ / 4); idx += 256) {
            int u  = idx >> 6;
            int d4 = idx & 63;
            float4 a = ((const float4*)(g_qu + (size_t)(b * U_ + u0 + u) * HID_))[d4];
            float4 qb = qb4[d4];
            a.x += qb.x; a.y += qb.y; a.z += qb.z; a.w += qb.w;
            ((float4*)qs)[u * 64 + d4] = a;
        }
    }
    // --- fill ks transposed ---
    for (int idx = tid; idx < 64 * (HID_ / 4); idx += 256) {
        int t  = idx >> 6;
        int d4 = idx & 63;
        float4 v = ((const float4*)(g_kh + (size_t)(b * T_ + t0 + t) * HID_))[d4];
        int d = d4 * 4;
        ks[(d + 0) * KS_STRIDE + t] = v.x;
        ks[(d + 1) * KS_STRIDE + t] = v.y;
        ks[(d + 2) * KS_STRIDE + t] = v.z;
        ks[(d + 3) * KS_STRIDE + t] = v.w;
    }
    // --- fw2 ---
    if (tid < HID_ / 4) ((float4*)fw2s)[tid] = ((const float4*)fw2)[tid];
    __syncthreads();

    const int tg = tid & 15;       // 4-t group
    const int u  = tid >> 4;       // 0..15
    const float4* qrow = (const float4*)(qs + u * HID_);
    const float4* w4   = (const float4*)fw2s;

    float4 acc = make_float4(0.f, 0.f, 0.f, 0.f);

    #pragma unroll 8
    for (int d4 = 0; d4 < HID_ / 4; ++d4) {
        float4 a = qrow[d4];
        float4 w = w4[d4];
        int d = d4 * 4;
        float4 k0 = *(const float4*)&ks[(d + 0) * KS_STRIDE + tg * 4];
        acc.x = fmaf(fmaxf(a.x + k0.x, 0.f), w.x, acc.x);
        acc.y = fmaf(fmaxf(a.x + k0.y, 0.f), w.x, acc.y);
        acc.z = fmaf(fmaxf(a.x + k0.z, 0.f), w.x, acc.z);
        acc.w = fmaf(fmaxf(a.x + k0.w, 0.f), w.x, acc.w);
        float4 k1 = *(const float4*)&ks[(d + 1) * KS_STRIDE + tg * 4];
        acc.x = fmaf(fmaxf(a.y + k1.x, 0.f), w.y, acc.x);
        acc.y = fmaf(fmaxf(a.y + k1.y, 0.f), w.y, acc.y);
        acc.z = fmaf(fmaxf(a.y + k1.z, 0.f), w.y, acc.z);
        acc.w = fmaf(fmaxf(a.y + k1.w, 0.f), w.y, acc.w);
        float4 k2 = *(const float4*)&ks[(d + 2) * KS_STRIDE + tg * 4];
        acc.x = fmaf(fmaxf(a.z + k2.x, 0.f), w.z, acc.x);
        acc.y = fmaf(fmaxf(a.z + k2.y, 0.f), w.z, acc.y);
        acc.z = fmaf(fmaxf(a.z + k2.z, 0.f), w.z, acc.z);
        acc.w = fmaf(fmaxf(a.z + k2.w, 0.f), w.z, acc.w);
        float4 k3 = *(const float4*)&ks[(d + 3) * KS_STRIDE + tg * 4];
        acc.x = fmaf(fmaxf(a.w + k3.x, 0.f), w.w, acc.x);
        acc.y = fmaf(fmaxf(a.w + k3.y, 0.f), w.w, acc.y);
        acc.z = fmaf(fmaxf(a.w + k3.z, 0.f), w.w, acc.z);
        acc.w = fmaf(fmaxf(a.w + k3.w, 0.f), w.w, acc.w);
    }

    float bias = fb2[0];
    acc.x += bias; acc.y += bias; acc.z += bias; acc.w += bias;

    size_t o = (((size_t)z * U_) + (u0 + u)) * T_ + t0 + tg * 4;
    *(float4*)(out + o) = acc;
}

// ---------------------------------------------------------------------------
extern "C" void kernel_launch(void* const* d_in, const int* in_sizes, int n_in,
                              void* d_out, int out_size)
{
    const float* uav_feat = (const float*)d_in[0];
    const float* task_feat = (const float*)d_in[1];
    const float* uw0 = (const float*)d_in[2];
    const float* ub0 = (const float*)d_in[3];
    const float* uw1 = (const float*)d_in[4];
    const float* ub1 = (const float*)d_in[5];
    const float* uw2 = (const float*)d_in[6];
    const float* ub2 = (const float*)d_in[7];
    const float* tw0 = (const float*)d_in[8];
    const float* tb0 = (const float*)d_in[9];
    const float* tw1 = (const float*)d_in[10];
    const float* tb1 = (const float*)d_in[11];
    const float* tw2 = (const float*)d_in[12];
    const float* tb2 = (const float*)d_in[13];
    const float* head_q = (const float*)d_in[14];
    const float* fw1 = (const float*)d_in[15];
    const float* fb1 = (const float*)d_in[16];
    const float* fw2 = (const float*)d_in[17];
    const float* fb2 = (const float*)d_in[18];
    float* out = (float*)d_out;

    cudaFuncSetAttribute(stageE_kernel,
                         cudaFuncAttributeMaxDynamicSharedMemorySize,
                         SMEM_E_BYTES);

    // Encoders (fused with fw1 projection)
    enc_kernel<<<(B_ * U_) / 16, 128>>>(uav_feat, uw0, ub0, uw1, ub1, uw2, ub2,
                                        fw1, 0, /*sel=*/0);
    enc_kernel<<<(B_ * T_) / 16, 128>>>(task_feat, tw0, tb0, tw1, tb1, tw2, tb2,
                                        fw1, E_, /*sel=*/1);
    qb_kernel<<<H_, 256>>>(head_q, fw1, fb1);

    dim3 grid(T_ / 64, U_ / 16, B_ * H_);
    stageE_kernel<<<grid, 256, SMEM_E_BYTES>>>(fw2, fb2, out);
}

// round 3
// speedup vs baseline: 1.9749x; 1.9749x over previous
#include <cuda_runtime.h>
#include <cstdint>

// Problem dims (fixed)
#define B_  16
#define U_  64
#define T_  128
#define E_  128
#define HID_ 256
#define H_  4
#define ENC_H_ 128
#define IN_DIM_ 32

// Scratch (device globals: no allocation allowed)
__device__ float g_qu[B_ * U_ * HID_];   // ue @ fw1[:E]          (1024 x 256)
__device__ float g_kh[B_ * T_ * HID_];   // te @ fw1[E:]          (2048 x 256)
__device__ float g_qb[H_ * HID_];        // head_q @ fw1[:E] + fb1 (4 x 256)

// ---------------------------------------------------------------------------
// Fused encoder kernel: blocks [0,64) = UAV rows, [64,192) = task rows,
// block 192 = qb computation. 256 threads; j = tid&127 owns output col j,
// half = tid>>7 owns 8 of the 16 rows in the block's tile.
// ---------------------------------------------------------------------------
__global__ __launch_bounds__(256) void enc_fused_kernel(
    const float* __restrict__ uav_feat, const float* __restrict__ task_feat,
    const float* __restrict__ uw0, const float* __restrict__ ub0,
    const float* __restrict__ uw1, const float* __restrict__ ub1,
    const float* __restrict__ uw2, const float* __restrict__ ub2,
    const float* __restrict__ tw0, const float* __restrict__ tb0,
    const float* __restrict__ tw1, const float* __restrict__ tb1,
    const float* __restrict__ tw2, const float* __restrict__ tb2,
    const float* __restrict__ head_q, const float* __restrict__ fw1,
    const float* __restrict__ fb1)
{
    const int bx = blockIdx.x;
    const int tid = threadIdx.x;

    // ---------------- qb block ----------------
    if (bx == 192) {
        int d = tid & 255;
        // 256 threads: each thread handles d for all 4 heads? 256 threads,
        // 4*256 outputs -> each thread does its d for all 4 h.
        #pragma unroll
        for (int h = 0; h < H_; ++h) {
            float acc = fb1[d];
            #pragma unroll 8
            for (int k = 0; k < E_; ++k)
                acc += head_q[h * E_ + k] * fw1[k * HID_ + d];
            g_qb[h * HID_ + d] = acc;
        }
        return;
    }

    const int is_task = (bx >= 64);
    const float* x  = is_task ? task_feat : uav_feat;
    const float* w0 = is_task ? tw0 : uw0;
    const float* b0 = is_task ? tb0 : ub0;
    const float* w1 = is_task ? tw1 : uw1;
    const float* b1 = is_task ? tb1 : ub1;
    const float* w2 = is_task ? tw2 : uw2;
    const float* b2 = is_task ? tb2 : ub2;
    float* out      = is_task ? g_kh : g_qu;
    const int fw1_off = is_task ? E_ : 0;
    const int row0 = (is_task ? (bx - 64) : bx) * 16;

    __shared__ float xs[16][IN_DIM_];
    __shared__ float bufA[16][ENC_H_];
    __shared__ float bufB[16][ENC_H_];

    // load 16x32 input tile
    for (int i = tid; i < 16 * IN_DIM_; i += 256) {
        xs[i >> 5][i & 31] = x[(row0 + (i >> 5)) * IN_DIM_ + (i & 31)];
    }
    __syncthreads();

    const int j = tid & 127;
    const int rb = (tid >> 7) * 8;   // row base: 0 or 8
    float acc[8];

    // ---- layer 0: 32 -> 128, relu ----
    #pragma unroll
    for (int r = 0; r < 8; ++r) acc[r] = b0[j];
    #pragma unroll
    for (int k = 0; k < IN_DIM_; k += 4) {
        float wv0 = w0[(k + 0) * ENC_H_ + j];
        float wv1 = w0[(k + 1) * ENC_H_ + j];
        float wv2 = w0[(k + 2) * ENC_H_ + j];
        float wv3 = w0[(k + 3) * ENC_H_ + j];
        #pragma unroll
        for (int r = 0; r < 8; ++r) {
            float4 xa = *(const float4*)&xs[rb + r][k];
            acc[r] += xa.x * wv0 + xa.y * wv1 + xa.z * wv2 + xa.w * wv3;
        }
    }
    #pragma unroll
    for (int r = 0; r < 8; ++r) bufA[rb + r][j] = fmaxf(acc[r], 0.f);
    __syncthreads();

    // ---- layer 1: 128 -> 128, relu ----
    #pragma unroll
    for (int r = 0; r < 8; ++r) acc[r] = b1[j];
    #pragma unroll 8
    for (int k = 0; k < ENC_H_; k += 4) {
        float wv0 = w1[(k + 0) * ENC_H_ + j];
        float wv1 = w1[(k + 1) * ENC_H_ + j];
        float wv2 = w1[(k + 2) * ENC_H_ + j];
        float wv3 = w1[(k + 3) * ENC_H_ + j];
        #pragma unroll
        for (int r = 0; r < 8; ++r) {
            float4 xa = *(const float4*)&bufA[rb + r][k];
            acc[r] += xa.x * wv0 + xa.y * wv1 + xa.z * wv2 + xa.w * wv3;
        }
    }
    #pragma unroll
    for (int r = 0; r < 8; ++r) bufB[rb + r][j] = fmaxf(acc[r], 0.f);
    __syncthreads();

    // ---- layer 2: 128 -> 128 (no relu) ----
    #pragma unroll
    for (int r = 0; r < 8; ++r) acc[r] = b2[j];
    #pragma unroll 8
    for (int k = 0; k < ENC_H_; k += 4) {
        float wv0 = w2[(k + 0) * ENC_H_ + j];
        float wv1 = w2[(k + 1) * ENC_H_ + j];
        float wv2 = w2[(k + 2) * ENC_H_ + j];
        float wv3 = w2[(k + 3) * ENC_H_ + j];
        #pragma unroll
        for (int r = 0; r < 8; ++r) {
            float4 xa = *(const float4*)&bufB[rb + r][k];
            acc[r] += xa.x * wv0 + xa.y * wv1 + xa.z * wv2 + xa.w * wv3;
        }
    }
    __syncthreads();   // bufA reads done; safe to overwrite
    #pragma unroll
    for (int r = 0; r < 8; ++r) bufA[rb + r][j] = acc[r];
    __syncthreads();

    // ---- projection through fw1 slice: 128 -> 256 ----
    #pragma unroll
    for (int p = 0; p < 2; ++p) {
        int col = j + p * 128;
        #pragma unroll
        for (int r = 0; r < 8; ++r) acc[r] = 0.f;
        #pragma unroll 8
        for (int k = 0; k < E_; k += 4) {
            float wv0 = fw1[(fw1_off + k + 0) * HID_ + col];
            float wv1 = fw1[(fw1_off + k + 1) * HID_ + col];
            float wv2 = fw1[(fw1_off + k + 2) * HID_ + col];
            float wv3 = fw1[(fw1_off + k + 3) * HID_ + col];
            #pragma unroll
            for (int r = 0; r < 8; ++r) {
                float4 xa = *(const float4*)&bufA[rb + r][k];
                acc[r] += xa.x * wv0 + xa.y * wv1 + xa.z * wv2 + xa.w * wv3;
            }
        }
        #pragma unroll
        for (int r = 0; r < 8; ++r)
            out[(size_t)(row0 + rb + r) * HID_ + col] = acc[r];
    }
}

// ---------------------------------------------------------------------------
// Stage E: logits[b,h,u,t] = fb2 + sum_d relu(qu[b,u,d]+qb[h,d]+kh[b,t,d])*fw2[d]
// Tile: 64u x 64t per block (all of U), 256 threads, 4u x 4t register tile
// per thread.  t's per thread strided by 16 (t = tg + 16*j) for bank-floor
// LDS.  qs[u][d] stride 256, ks[t][d] stride 260 (==4 mod 32 banks).
// ---------------------------------------------------------------------------
#define KSTRIDE 260
#define SMEM_E_FLOATS (64 * HID_ + 64 * KSTRIDE + HID_)
#define SMEM_E_BYTES  (SMEM_E_FLOATS * 4)

__global__ __launch_bounds__(256) void stageE_kernel(
    const float* __restrict__ fw2, const float* __restrict__ fb2,
    float* __restrict__ out)
{
    extern __shared__ float smem[];
    float* qs   = smem;                       // [64][256]
    float* ks   = smem + 64 * HID_;           // [64][260]
    float* fw2s = ks + 64 * KSTRIDE;          // [256]

    const int tid = threadIdx.x;
    const int t0 = blockIdx.x * 64;
    const int z  = blockIdx.y;                // b*H + h
    const int b  = z >> 2;
    const int h  = z & 3;

    // --- fill qs = qu + qb (float4, coalesced, conflict-free) ---
    {
        const float4* qb4 = (const float4*)(g_qb + h * HID_);
        const float4* qu4 = (const float4*)(g_qu + (size_t)b * U_ * HID_);
        for (int idx = tid; idx < 64 * (HID_ / 4); idx += 256) {
            int u  = idx >> 6;
            int d4 = idx & 63;
            float4 a = qu4[u * 64 + d4];
            float4 qb = qb4[d4];
            a.x += qb.x; a.y += qb.y; a.z += qb.z; a.w += qb.w;
            ((float4*)(qs + u * HID_))[d4] = a;
        }
    }
    // --- fill ks (row-major [t][d], stride 260) ---
    {
        const float4* kh4 = (const float4*)(g_kh + (size_t)(b * T_ + t0) * HID_);
        for (int idx = tid; idx < 64 * (HID_ / 4); idx += 256) {
            int t  = idx >> 6;
            int d4 = idx & 63;
            ((float4*)(ks + t * KSTRIDE))[d4] = kh4[t * 64 + d4];
        }
    }
    // --- fw2 ---
    if (tid < HID_ / 4) ((float4*)fw2s)[tid] = ((const float4*)fw2)[tid];
    __syncthreads();

    const int tg = tid & 15;       // t = t0 + tg + 16*j
    const int ug = tid >> 4;       // u = ug*4 + i

    float acc[4][4];
    #pragma unroll
    for (int i = 0; i < 4; ++i)
        #pragma unroll
        for (int jj = 0; jj < 4; ++jj) acc[i][jj] = 0.f;

    const float* qbase = qs + (ug * 4) * HID_;
    const float* kbase = ks + tg * KSTRIDE;

    #pragma unroll 2
    for (int d4 = 0; d4 < HID_ / 4; ++d4) {
        float4 wv = ((const float4*)fw2s)[d4];
        float4 qv[4], kv[4];
        #pragma unroll
        for (int i = 0; i < 4; ++i)
            qv[i] = *(const float4*)(qbase + i * HID_ + d4 * 4);
        #pragma unroll
        for (int jj = 0; jj < 4; ++jj)
            kv[jj] = *(const float4*)(kbase + jj * 16 * KSTRIDE + d4 * 4);

        #pragma unroll
        for (int i = 0; i < 4; ++i) {
            // dd = 0
            acc[i][0] = fmaf(fmaxf(qv[i].x + kv[0].x, 0.f), wv.x, acc[i][0]);
            acc[i][1] = fmaf(fmaxf(qv[i].x + kv[1].x, 0.f), wv.x, acc[i][1]);
            acc[i][2] = fmaf(fmaxf(qv[i].x + kv[2].x, 0.f), wv.x, acc[i][2]);
            acc[i][3] = fmaf(fmaxf(qv[i].x + kv[3].x, 0.f), wv.x, acc[i][3]);
            // dd = 1
            acc[i][0] = fmaf(fmaxf(qv[i].y + kv[0].y, 0.f), wv.y, acc[i][0]);
            acc[i][1] = fmaf(fmaxf(qv[i].y + kv[1].y, 0.f), wv.y, acc[i][1]);
            acc[i][2] = fmaf(fmaxf(qv[i].y + kv[2].y, 0.f), wv.y, acc[i][2]);
            acc[i][3] = fmaf(fmaxf(qv[i].y + kv[3].y, 0.f), wv.y, acc[i][3]);
            // dd = 2
            acc[i][0] = fmaf(fmaxf(qv[i].z + kv[0].z, 0.f), wv.z, acc[i][0]);
            acc[i][1] = fmaf(fmaxf(qv[i].z + kv[1].z, 0.f), wv.z, acc[i][1]);
            acc[i][2] = fmaf(fmaxf(qv[i].z + kv[2].z, 0.f), wv.z, acc[i][2]);
            acc[i][3] = fmaf(fmaxf(qv[i].z + kv[3].z, 0.f), wv.z, acc[i][3]);
            // dd = 3
            acc[i][0] = fmaf(fmaxf(qv[i].w + kv[0].w, 0.f), wv.w, acc[i][0]);
            acc[i][1] = fmaf(fmaxf(qv[i].w + kv[1].w, 0.f), wv.w, acc[i][1]);
            acc[i][2] = fmaf(fmaxf(qv[i].w + kv[2].w, 0.f), wv.w, acc[i][2]);
            acc[i][3] = fmaf(fmaxf(qv[i].w + kv[3].w, 0.f), wv.w, acc[i][3]);
        }
    }

    const float bias = fb2[0];
    // out[z][u][t]: u = ug*4+i, t = t0 + tg + 16*jj
    #pragma unroll
    for (int i = 0; i < 4; ++i) {
        size_t base = ((size_t)z * U_ + (ug * 4 + i)) * T_ + t0 + tg;
        #pragma unroll
        for (int jj = 0; jj < 4; ++jj)
            out[base + jj * 16] = acc[i][jj] + bias;
    }
}

// ---------------------------------------------------------------------------
extern "C" void kernel_launch(void* const* d_in, const int* in_sizes, int n_in,
                              void* d_out, int out_size)
{
    const float* uav_feat = (const float*)d_in[0];
    const float* task_feat = (const float*)d_in[1];
    const float* uw0 = (const float*)d_in[2];
    const float* ub0 = (const float*)d_in[3];
    const float* uw1 = (const float*)d_in[4];
    const float* ub1 = (const float*)d_in[5];
    const float* uw2 = (const float*)d_in[6];
    const float* ub2 = (const float*)d_in[7];
    const float* tw0 = (const float*)d_in[8];
    const float* tb0 = (const float*)d_in[9];
    const float* tw1 = (const float*)d_in[10];
    const float* tb1 = (const float*)d_in[11];
    const float* tw2 = (const float*)d_in[12];
    const float* tb2 = (const float*)d_in[13];
    const float* head_q = (const float*)d_in[14];
    const float* fw1 = (const float*)d_in[15];
    const float* fb1 = (const float*)d_in[16];
    const float* fw2 = (const float*)d_in[17];
    const float* fb2 = (const float*)d_in[18];
    float* out = (float*)d_out;

    cudaFuncSetAttribute(stageE_kernel,
                         cudaFuncAttributeMaxDynamicSharedMemorySize,
                         SMEM_E_BYTES);

    // One fused launch: 64 uav blocks + 128 task blocks + 1 qb block
    enc_fused_kernel<<<193, 256>>>(uav_feat, task_feat,
                                   uw0, ub0, uw1, ub1, uw2, ub2,
                                   tw0, tb0, tw1, tb1, tw2, tb2,
                                   head_q, fw1, fb1);

    dim3 grid(T_ / 64, B_ * H_);
    stageE_kernel<<<grid, 256, SMEM_E_BYTES>>>(fw2, fb2, out);
}

// round 5
// speedup vs baseline: 2.2501x; 1.1394x over previous
#include <cuda_runtime.h>
#include <cstdint>

// Problem dims (fixed)
#define B_  16
#define U_  64
#define T_  128
#define E_  128
#define HID_ 256
#define H_  4
#define ENC_H_ 128
#define IN_DIM_ 32

typedef unsigned long long ull;

// Scratch (device globals: no allocation allowed)
__device__ float g_qu[B_ * U_ * HID_];   // ue @ fw1[:E]          (1024 x 256)
__device__ float g_kh[B_ * T_ * HID_];   // te @ fw1[E:]          (2048 x 256)
__device__ float g_qb[H_ * HID_];        // head_q @ fw1[:E] + fb1 (4 x 256)

// ---- packed f32x2 helpers (Blackwell) ----
__device__ __forceinline__ ull add2(ull a, ull b) {
    ull r;
    asm("add.rn.f32x2 %0, %1, %2;" : "=l"(r) : "l"(a), "l"(b));
    return r;
}
__device__ __forceinline__ void fma2(ull& acc, ull a, ull b) {
    asm("fma.rn.f32x2 %0, %1, %2, %0;" : "+l"(acc) : "l"(a), "l"(b));
}
__device__ __forceinline__ ull relu2(ull x) {
    float lo, hi;
    asm("mov.b64 {%0,%1}, %2;" : "=f"(lo), "=f"(hi) : "l"(x));
    lo = fmaxf(lo, 0.f);
    hi = fmaxf(hi, 0.f);
    ull r;
    asm("mov.b64 %0, {%1,%2};" : "=l"(r) : "f"(lo), "f"(hi));
    return r;
}
__device__ __forceinline__ float hsum2(ull x) {
    float lo, hi;
    asm("mov.b64 {%0,%1}, %2;" : "=f"(lo), "=f"(hi) : "l"(x));
    return lo + hi;
}

// ---------------------------------------------------------------------------
// Fused encoder kernel: blocks [0,64) = UAV rows, [64,192) = task rows,
// block 192 = qb.  512 threads: j = tid&127 owns output col j,
// quarter = tid>>7 owns 4 of the 16 rows.
// ---------------------------------------------------------------------------
__global__ __launch_bounds__(512) void enc_fused_kernel(
    const float* __restrict__ uav_feat, const float* __restrict__ task_feat,
    const float* __restrict__ uw0, const float* __restrict__ ub0,
    const float* __restrict__ uw1, const float* __restrict__ ub1,
    const float* __restrict__ uw2, const float* __restrict__ ub2,
    const float* __restrict__ tw0, const float* __restrict__ tb0,
    const float* __restrict__ tw1, const float* __restrict__ tb1,
    const float* __restrict__ tw2, const float* __restrict__ tb2,
    const float* __restrict__ head_q, const float* __restrict__ fw1,
    const float* __restrict__ fb1)
{
    const int bx = blockIdx.x;
    const int tid = threadIdx.x;

    // ---------------- qb block ----------------
    if (bx == 192) {
        int d  = tid & 255;
        int h0 = tid >> 8;           // 0..1
        #pragma unroll
        for (int h = h0; h < H_; h += 2) {
            float acc = fb1[d];
            #pragma unroll 8
            for (int k = 0; k < E_; ++k)
                acc += head_q[h * E_ + k] * fw1[k * HID_ + d];
            g_qb[h * HID_ + d] = acc;
        }
        return;
    }

    const int is_task = (bx >= 64);
    const float* x  = is_task ? task_feat : uav_feat;
    const float* w0 = is_task ? tw0 : uw0;
    const float* b0 = is_task ? tb0 : ub0;
    const float* w1 = is_task ? tw1 : uw1;
    const float* b1 = is_task ? tb1 : ub1;
    const float* w2 = is_task ? tw2 : uw2;
    const float* b2 = is_task ? tb2 : ub2;
    float* out      = is_task ? g_kh : g_qu;
    const int fw1_off = is_task ? E_ : 0;
    const int row0 = (is_task ? (bx - 64) : bx) * 16;

    __shared__ float xs[16][IN_DIM_];
    __shared__ float bufA[16][ENC_H_];
    __shared__ float bufB[16][ENC_H_];

    // load 16x32 input tile
    if (tid < 16 * IN_DIM_)
        xs[tid >> 5][tid & 31] = x[(row0 + (tid >> 5)) * IN_DIM_ + (tid & 31)];
    __syncthreads();

    const int j  = tid & 127;
    const int rb = (tid >> 7) * 4;   // row base: 0,4,8,12
    float acc[4];

    // ---- layer 0: 32 -> 128, relu ----
    #pragma unroll
    for (int r = 0; r < 4; ++r) acc[r] = b0[j];
    #pragma unroll
    for (int k = 0; k < IN_DIM_; k += 4) {
        float wv0 = w0[(k + 0) * ENC_H_ + j];
        float wv1 = w0[(k + 1) * ENC_H_ + j];
        float wv2 = w0[(k + 2) * ENC_H_ + j];
        float wv3 = w0[(k + 3) * ENC_H_ + j];
        #pragma unroll
        for (int r = 0; r < 4; ++r) {
            float4 xa = *(const float4*)&xs[rb + r][k];
            acc[r] += xa.x * wv0 + xa.y * wv1 + xa.z * wv2 + xa.w * wv3;
        }
    }
    #pragma unroll
    for (int r = 0; r < 4; ++r) bufA[rb + r][j] = fmaxf(acc[r], 0.f);
    __syncthreads();

    // ---- layer 1: 128 -> 128, relu ----
    #pragma unroll
    for (int r = 0; r < 4; ++r) acc[r] = b1[j];
    #pragma unroll 8
    for (int k = 0; k < ENC_H_; k += 4) {
        float wv0 = w1[(k + 0) * ENC_H_ + j];
        float wv1 = w1[(k + 1) * ENC_H_ + j];
        float wv2 = w1[(k + 2) * ENC_H_ + j];
        float wv3 = w1[(k + 3) * ENC_H_ + j];
        #pragma unroll
        for (int r = 0; r < 4; ++r) {
            float4 xa = *(const float4*)&bufA[rb + r][k];
            acc[r] += xa.x * wv0 + xa.y * wv1 + xa.z * wv2 + xa.w * wv3;
        }
    }
    #pragma unroll
    for (int r = 0; r < 4; ++r) bufB[rb + r][j] = fmaxf(acc[r], 0.f);
    __syncthreads();

    // ---- layer 2: 128 -> 128 (no relu) ----
    #pragma unroll
    for (int r = 0; r < 4; ++r) acc[r] = b2[j];
    #pragma unroll 8
    for (int k = 0; k < ENC_H_; k += 4) {
        float wv0 = w2[(k + 0) * ENC_H_ + j];
        float wv1 = w2[(k + 1) * ENC_H_ + j];
        float wv2 = w2[(k + 2) * ENC_H_ + j];
        float wv3 = w2[(k + 3) * ENC_H_ + j];
        #pragma unroll
        for (int r = 0; r < 4; ++r) {
            float4 xa = *(const float4*)&bufB[rb + r][k];
            acc[r] += xa.x * wv0 + xa.y * wv1 + xa.z * wv2 + xa.w * wv3;
        }
    }
    __syncthreads();   // bufA reads done; safe to overwrite
    #pragma unroll
    for (int r = 0; r < 4; ++r) bufA[rb + r][j] = acc[r];
    __syncthreads();

    // ---- projection through fw1 slice: 128 -> 256 ----
    #pragma unroll
    for (int p = 0; p < 2; ++p) {
        int col = j + p * 128;
        #pragma unroll
        for (int r = 0; r < 4; ++r) acc[r] = 0.f;
        #pragma unroll 8
        for (int k = 0; k < E_; k += 4) {
            float wv0 = fw1[(fw1_off + k + 0) * HID_ + col];
            float wv1 = fw1[(fw1_off + k + 1) * HID_ + col];
            float wv2 = fw1[(fw1_off + k + 2) * HID_ + col];
            float wv3 = fw1[(fw1_off + k + 3) * HID_ + col];
            #pragma unroll
            for (int r = 0; r < 4; ++r) {
                float4 xa = *(const float4*)&bufA[rb + r][k];
                acc[r] += xa.x * wv0 + xa.y * wv1 + xa.z * wv2 + xa.w * wv3;
            }
        }
        #pragma unroll
        for (int r = 0; r < 4; ++r)
            out[(size_t)(row0 + rb + r) * HID_ + col] = acc[r];
    }
}

// ---------------------------------------------------------------------------
// Stage E: logits[b,h,u,t] = fb2 + sum_d relu(qu[b,u,d]+qb[h,d]+kh[b,t,d])*fw2[d]
// Tile 64u x 64t, 512 threads, thread tile 2u x 4t, d packed as f32x2 pairs.
// ---------------------------------------------------------------------------
#define KSTRIDE 260
#define SMEM_E_FLOATS (64 * HID_ + 64 * KSTRIDE + HID_)
#define SMEM_E_BYTES  (SMEM_E_FLOATS * 4)

__global__ __launch_bounds__(512) void stageE_kernel(
    const float* __restrict__ fw2, const float* __restrict__ fb2,
    float* __restrict__ out)
{
    extern __shared__ float smem[];
    float* qs   = smem;                       // [64][256]
    float* ks   = smem + 64 * HID_;           // [64][260]
    float* fw2s = ks + 64 * KSTRIDE;          // [256]

    const int tid = threadIdx.x;
    const int t0 = blockIdx.x * 64;
    const int z  = blockIdx.y;                // b*H + h
    const int b  = z >> 2;
    const int h  = z & 3;

    // --- fill qs = qu + qb (float4, coalesced, conflict-free) ---
    {
        const float4* qb4 = (const float4*)(g_qb + h * HID_);
        const float4* qu4 = (const float4*)(g_qu + (size_t)b * U_ * HID_);
        for (int idx = tid; idx < 64 * (HID_ / 4); idx += 512) {
            int u  = idx >> 6;
            int d4 = idx & 63;
            float4 a = qu4[u * 64 + d4];
            float4 qb = qb4[d4];
            a.x += qb.x; a.y += qb.y; a.z += qb.z; a.w += qb.w;
            ((float4*)(qs + u * HID_))[d4] = a;
        }
    }
    // --- fill ks (row-major [t][d], stride 260) ---
    {
        const float4* kh4 = (const float4*)(g_kh + (size_t)(b * T_ + t0) * HID_);
        for (int idx = tid; idx < 64 * (HID_ / 4); idx += 512) {
            int t  = idx >> 6;
            int d4 = idx & 63;
            ((float4*)(ks + t * KSTRIDE))[d4] = kh4[t * 64 + d4];
        }
    }
    // --- fw2 ---
    if (tid < HID_ / 4) ((float4*)fw2s)[tid] = ((const float4*)fw2)[tid];
    __syncthreads();

    const int tg = tid & 15;       // t = t0 + tg + 16*jj
    const int ug = tid >> 4;       // u = ug*2 + i, ug in 0..31

    ull acc[2][4];
    #pragma unroll
    for (int i = 0; i < 2; ++i)
        #pragma unroll
        for (int jj = 0; jj < 4; ++jj) acc[i][jj] = 0ULL;

    const float* qbase = qs + (ug * 2) * HID_;
    const float* kbase = ks + tg * KSTRIDE;

    #pragma unroll 4
    for (int d4 = 0; d4 < HID_ / 4; ++d4) {
        // each float4 = two f32x2 pairs (d even/odd interleaved naturally)
        ulonglong2 wv = *(const ulonglong2*)(fw2s + d4 * 4);
        ulonglong2 qv[2], kv[4];
        #pragma unroll
        for (int i = 0; i < 2; ++i)
            qv[i] = *(const ulonglong2*)(qbase + i * HID_ + d4 * 4);
        #pragma unroll
        for (int jj = 0; jj < 4; ++jj)
            kv[jj] = *(const ulonglong2*)(kbase + jj * 16 * KSTRIDE + d4 * 4);

        #pragma unroll
        for (int i = 0; i < 2; ++i) {
            #pragma unroll
            for (int jj = 0; jj < 4; ++jj) {
                fma2(acc[i][jj], relu2(add2(qv[i].x, kv[jj].x)), wv.x);
                fma2(acc[i][jj], relu2(add2(qv[i].y, kv[jj].y)), wv.y);
            }
        }
    }

    const float bias = fb2[0];
    #pragma unroll
    for (int i = 0; i < 2; ++i) {
        size_t base = ((size_t)z * U_ + (ug * 2 + i)) * T_ + t0 + tg;
        #pragma unroll
        for (int jj = 0; jj < 4; ++jj)
            out[base + jj * 16] = hsum2(acc[i][jj]) + bias;
    }
}

// ---------------------------------------------------------------------------
extern "C" void kernel_launch(void* const* d_in, const int* in_sizes, int n_in,
                              void* d_out, int out_size)
{
    const float* uav_feat = (const float*)d_in[0];
    const float* task_feat = (const float*)d_in[1];
    const float* uw0 = (const float*)d_in[2];
    const float* ub0 = (const float*)d_in[3];
    const float* uw1 = (const float*)d_in[4];
    const float* ub1 = (const float*)d_in[5];
    const float* uw2 = (const float*)d_in[6];
    const float* ub2 = (const float*)d_in[7];
    const float* tw0 = (const float*)d_in[8];
    const float* tb0 = (const float*)d_in[9];
    const float* tw1 = (const float*)d_in[10];
    const float* tb1 = (const float*)d_in[11];
    const float* tw2 = (const float*)d_in[12];
    const float* tb2 = (const float*)d_in[13];
    const float* head_q = (const float*)d_in[14];
    const float* fw1 = (const float*)d_in[15];
    const float* fb1 = (const float*)d_in[16];
    const float* fw2 = (const float*)d_in[17];
    const float* fb2 = (const float*)d_in[18];
    float* out = (float*)d_out;

    cudaFuncSetAttribute(stageE_kernel,
                         cudaFuncAttributeMaxDynamicSharedMemorySize,
                         SMEM_E_BYTES);

    // One fused launch: 64 uav blocks + 128 task blocks + 1 qb block
    enc_fused_kernel<<<193, 512>>>(uav_feat, task_feat,
                                   uw0, ub0, uw1, ub1, uw2, ub2,
                                   tw0, tb0, tw1, tb1, tw2, tb2,
                                   head_q, fw1, fb1);

    dim3 grid(T_ / 64, B_ * H_);
    stageE_kernel<<<grid, 512, SMEM_E_BYTES>>>(fw2, fb2, out);
}